// round 9
// baseline (speedup 1.0000x reference)
#include <cuda_runtime.h>
#include <cuda_fp16.h>
#include <cstdint>

#define SEQ   2048
#define BATCH 64
#define DIM   512
#define HID   512
#define GATE  2048   // 4*HID
#define NG    4      // independent batch groups
#define GSZ   16     // CTAs per group (one per 32 h-cols)
#define BPG   16     // batches per group

// ---------------- device scratch ---------------------------------------------
__device__ float  g_xg[(size_t)SEQ * BATCH * GATE];  // precomputed input gates
__device__ __half g_hh[2][BATCH * HID];              // double-buffered hidden state (fp16)

struct alignas(128) PadU { unsigned v; unsigned pad[31]; };
__device__ PadU g_cnt[NG];          // per-group arrive counters (always 0 at quiescence)
__device__ PadU g_flag[NG][GSZ];    // per-CTA generation flags (private L2 lines)

// ---------------- helpers ----------------------------------------------------
__device__ __forceinline__ uint32_t pack_h2(float a, float b) {
    __half2 h = __floats2half2_rn(a, b);
    return *reinterpret_cast<uint32_t*>(&h);
}
__device__ __forceinline__ uint32_t ldcg_u32(const void* p) {
    uint32_t v;
    asm volatile("ld.global.cg.b32 %0, [%1];" : "=r"(v) : "l"(p));
    return v;
}
__device__ __forceinline__ void mma_f16(float* c, const uint32_t* a, const uint32_t* b) {
    asm volatile(
        "mma.sync.aligned.m16n8k16.row.col.f32.f16.f16.f32 "
        "{%0,%1,%2,%3}, {%4,%5,%6,%7}, {%8,%9}, {%0,%1,%2,%3};"
        : "+f"(c[0]), "+f"(c[1]), "+f"(c[2]), "+f"(c[3])
        : "r"(a[0]), "r"(a[1]), "r"(a[2]), "r"(a[3]), "r"(b[0]), "r"(b[1]));
}
__device__ __forceinline__ float sigf(float x) { return 1.0f / (1.0f + __expf(-x)); }
__device__ __forceinline__ float tanhfast(float x) { return 2.0f / (1.0f + __expf(-2.0f * x)) - 1.0f; }

// =============================================================================
// Phase 1: Xg = x @ W_ih^T + (b_ih + b_hh)   (unchanged — proven in R6)
// =============================================================================
__global__ __launch_bounds__(256) void lstm_xgemm(
    const float* __restrict__ x, const float* __restrict__ Wih,
    const float* __restrict__ bih, const float* __restrict__ bhh)
{
    __shared__ __half As[128 * 40];
    __shared__ __half Bs[128 * 40];
    __shared__ float  bsum[128];

    const int t = threadIdx.x;
    const int warp = t >> 5, lane = t & 31;
    const int wm = warp & 1;
    const int wn = warp >> 1;
    const int g = lane >> 2, tig = lane & 3;
    const int m0 = blockIdx.y * 128;
    const int n0 = blockIdx.x * 128;

    if (t < 128) bsum[t] = bih[n0 + t] + bhh[n0 + t];

    float acc[4][4][4];
#pragma unroll
    for (int mt = 0; mt < 4; mt++)
#pragma unroll
        for (int nt = 0; nt < 4; nt++)
#pragma unroll
            for (int i = 0; i < 4; i++) acc[mt][nt][i] = 0.f;

    for (int kc = 0; kc < 512; kc += 32) {
        __syncthreads();
#pragma unroll
        for (int i = 0; i < 4; i++) {
            int f = t + i * 256;
            int row = f >> 3, q = (f & 7) * 4;
            float4 v = *reinterpret_cast<const float4*>(x + (size_t)(m0 + row) * 512 + kc + q);
            __half2* d = reinterpret_cast<__half2*>(As + row * 40 + q);
            d[0] = __floats2half2_rn(v.x, v.y);
            d[1] = __floats2half2_rn(v.z, v.w);
        }
#pragma unroll
        for (int i = 0; i < 4; i++) {
            int f = t + i * 256;
            int row = f >> 3, q = (f & 7) * 4;
            float4 v = *reinterpret_cast<const float4*>(Wih + (size_t)(n0 + row) * 512 + kc + q);
            __half2* d = reinterpret_cast<__half2*>(Bs + row * 40 + q);
            d[0] = __floats2half2_rn(v.x, v.y);
            d[1] = __floats2half2_rn(v.z, v.w);
        }
        __syncthreads();

#pragma unroll
        for (int kt = 0; kt < 2; kt++) {
            const int k0 = kt * 16;
            uint32_t a[4][4], b[4][2];
#pragma unroll
            for (int mt = 0; mt < 4; mt++) {
                const int r = wm * 64 + mt * 16;
                a[mt][0] = *reinterpret_cast<const uint32_t*>(As + (r + g)     * 40 + k0 + 2 * tig);
                a[mt][1] = *reinterpret_cast<const uint32_t*>(As + (r + g + 8) * 40 + k0 + 2 * tig);
                a[mt][2] = *reinterpret_cast<const uint32_t*>(As + (r + g)     * 40 + k0 + 2 * tig + 8);
                a[mt][3] = *reinterpret_cast<const uint32_t*>(As + (r + g + 8) * 40 + k0 + 2 * tig + 8);
            }
#pragma unroll
            for (int nt = 0; nt < 4; nt++) {
                const int rn = wn * 32 + nt * 8;
                b[nt][0] = *reinterpret_cast<const uint32_t*>(Bs + (rn + g) * 40 + k0 + 2 * tig);
                b[nt][1] = *reinterpret_cast<const uint32_t*>(Bs + (rn + g) * 40 + k0 + 2 * tig + 8);
            }
#pragma unroll
            for (int mt = 0; mt < 4; mt++)
#pragma unroll
                for (int nt = 0; nt < 4; nt++)
                    mma_f16(acc[mt][nt], a[mt], b[nt]);
        }
    }

#pragma unroll
    for (int mt = 0; mt < 4; mt++) {
        const int r0 = m0 + wm * 64 + mt * 16 + g;
#pragma unroll
        for (int nt = 0; nt < 4; nt++) {
            const int cl = wn * 32 + nt * 8 + 2 * tig;
            const float b0 = bsum[cl], b1 = bsum[cl + 1];
            float2 v0 = make_float2(acc[mt][nt][0] + b0, acc[mt][nt][1] + b1);
            float2 v1 = make_float2(acc[mt][nt][2] + b0, acc[mt][nt][3] + b1);
            *reinterpret_cast<float2*>(g_xg + (size_t)r0 * GATE + n0 + cl)       = v0;
            *reinterpret_cast<float2*>(g_xg + (size_t)(r0 + 8) * GATE + n0 + cl) = v1;
        }
    }
}

// =============================================================================
// Phase 2: batch-partitioned persistent recurrence.
// 4 independent groups x 16 CTAs. Group bg owns batches [16bg, 16bg+16).
// Sense-reversing barrier (run-invariant across graph replays): each CTA
// reads its OWN private flag line at entry (gv), 16-way atomic arrive; leader
// resets counter and release-stores gv+1 to all 16 flags; waiters poll their
// own line for a change. No shared poll line -> no L2 serialization.
// =============================================================================
__device__ __forceinline__ void gbar(int bg, int cta) {
    __syncthreads();
    if (threadIdx.x == 0) {
        unsigned* myflag = &g_flag[bg][cta].v;
        unsigned gv;
        asm volatile("ld.acquire.gpu.global.u32 %0, [%1];" : "=r"(gv) : "l"(myflag) : "memory");
        unsigned old;
        asm volatile("atom.acq_rel.gpu.global.add.u32 %0, [%1], %2;"
                     : "=r"(old) : "l"(&g_cnt[bg].v), "r"(1u) : "memory");
        if (old == GSZ - 1u) {
            asm volatile("st.relaxed.gpu.global.u32 [%0], %1;"
                         :: "l"(&g_cnt[bg].v), "r"(0u) : "memory");
#pragma unroll
            for (int i = 0; i < GSZ; i++)
                asm volatile("st.release.gpu.global.u32 [%0], %1;"
                             :: "l"(&g_flag[bg][i].v), "r"(gv + 1u) : "memory");
        } else {
            unsigned cur;
            do {
                asm volatile("ld.acquire.gpu.global.u32 %0, [%1];"
                             : "=r"(cur) : "l"(myflag) : "memory");
            } while (cur == gv);
        }
    }
    __syncthreads();
}

__global__ __launch_bounds__(256, 1) void lstm_rec3(const float* __restrict__ Whh,
                                                    float* __restrict__ out)
{
    extern __shared__ float part[];   // [8 warps][128 rows][18] = 73728 B
    const int t = threadIdx.x, warp = t >> 5, lane = t & 31;
    const int g = lane >> 2, tig = lane & 3;
    const int bg  = blockIdx.x >> 4;       // batch group 0..3
    const int cta = blockIdx.x & 15;       // col group 0..15
    const int C0  = cta * 32;              // h-col base
    const int NB0 = bg * BPG;              // batch base
    const int ks  = warp * 64;             // this warp's k-slice

    // ---- resident W_hh fragments: 128 packed rows (m = q*32 + j), fp16 ----
    uint32_t wfr[8][4][4];                 // [mtile][ktile][reg] = 128 regs
#pragma unroll
    for (int mt = 0; mt < 8; mt++) {
        const int row_lo = mt * 16 + g;
        const int row_hi = row_lo + 8;
        const float* wlo = Whh + (size_t)((row_lo >> 5) * 512 + C0 + (row_lo & 31)) * 512;
        const float* whi = Whh + (size_t)((row_hi >> 5) * 512 + C0 + (row_hi & 31)) * 512;
#pragma unroll
        for (int kt = 0; kt < 4; kt++) {
            const int k = ks + kt * 16 + 2 * tig;
            wfr[mt][kt][0] = pack_h2(wlo[k],     wlo[k + 1]);
            wfr[mt][kt][1] = pack_h2(whi[k],     whi[k + 1]);
            wfr[mt][kt][2] = pack_h2(wlo[k + 8], wlo[k + 9]);
            wfr[mt][kt][3] = pack_h2(whi[k + 8], whi[k + 9]);
        }
    }

    // output mapping: thread owns (batch cb, col pair cp)
    const int cb = t >> 4;                 // 0..15 local batch
    const int cp = t & 15;                 // 0..15 col pair
    const int gb = NB0 + cb;               // global batch
    const int gc = C0 + 2 * cp;            // global h-col

    // init h0 = 0 for this CTA's (batch, col) slice
    *reinterpret_cast<uint32_t*>(&g_hh[0][gb * HID + gc]) = 0u;
    float c0 = 0.f, c1 = 0.f, hv0 = 0.f, hv1 = 0.f;

    gbar(bg, cta);

    int p = 0;
    for (int s = 0; s < SEQ; s++) {
        // ---- B fragments: h[16 batches, k-slice] from L2 ----
        uint32_t bb[2][4][2];
        const __half* hsrc = g_hh[p];
#pragma unroll
        for (int nt = 0; nt < 2; nt++)
#pragma unroll
            for (int kt = 0; kt < 4; kt++) {
                const __half* hp = hsrc + (size_t)(NB0 + nt * 8 + g) * HID + ks + kt * 16 + 2 * tig;
                bb[nt][kt][0] = ldcg_u32(hp);
                bb[nt][kt][1] = ldcg_u32(hp + 8);
            }

        // ---- Xg loads (independent; fill load latency) ----
        float xg[4][2];
        {
            const float* xb = g_xg + ((size_t)s * BATCH + gb) * GATE + gc;
#pragma unroll
            for (int q = 0; q < 4; q++) {
                float2 u = *reinterpret_cast<const float2*>(xb + q * 512);
                xg[q][0] = u.x; xg[q][1] = u.y;
            }
        }

        // ---- 64 mma: gates[128, 16] partial over this warp's K=64 ----
        float acc[8][2][4];
#pragma unroll
        for (int mt = 0; mt < 8; mt++)
#pragma unroll
            for (int nt = 0; nt < 2; nt++)
#pragma unroll
                for (int i = 0; i < 4; i++) acc[mt][nt][i] = 0.f;
#pragma unroll
        for (int kt = 0; kt < 4; kt++)
#pragma unroll
            for (int mt = 0; mt < 8; mt++)
#pragma unroll
                for (int nt = 0; nt < 2; nt++)
                    mma_f16(acc[mt][nt], wfr[mt][kt], bb[nt][kt]);

        // ---- store k-partials: [warp][row 128][batch 16 pad 18] ----
        float* pw = part + warp * (128 * 18);
#pragma unroll
        for (int mt = 0; mt < 8; mt++)
#pragma unroll
            for (int nt = 0; nt < 2; nt++) {
                const int row = mt * 16 + g, col = nt * 8 + 2 * tig;
                *reinterpret_cast<float2*>(pw + row * 18 + col) =
                    make_float2(acc[mt][nt][0], acc[mt][nt][1]);
                *reinterpret_cast<float2*>(pw + (row + 8) * 18 + col) =
                    make_float2(acc[mt][nt][2], acc[mt][nt][3]);
            }
        __syncthreads();

        // ---- reduce 8 partials + activations + state update ----
        float sg[4][2];
#pragma unroll
        for (int q = 0; q < 4; q++)
#pragma unroll
            for (int jj = 0; jj < 2; jj++) {
                const int row = q * 32 + 2 * cp + jj;
                const int base = row * 18 + cb;
                float v = part[base];
#pragma unroll
                for (int w = 1; w < 8; w++) v += part[w * (128 * 18) + base];
                sg[q][jj] = v;
            }

        const float i0 = sigf(xg[0][0] + sg[0][0]);
        const float i1 = sigf(xg[0][1] + sg[0][1]);
        const float f0 = sigf(xg[1][0] + sg[1][0]);
        const float f1 = sigf(xg[1][1] + sg[1][1]);
        const float g0 = tanhfast(xg[2][0] + sg[2][0]);
        const float g1 = tanhfast(xg[2][1] + sg[2][1]);
        const float o0 = sigf(xg[3][0] + sg[3][0]);
        const float o1 = sigf(xg[3][1] + sg[3][1]);

        c0 = f0 * c0 + i0 * g0;
        c1 = f1 * c1 + i1 * g1;
        hv0 = o0 * tanhfast(c0);
        hv1 = o1 * tanhfast(c1);

        // publish h (fp16, plain store — ordered by barrier release chain) + output
        *reinterpret_cast<uint32_t*>(&g_hh[p ^ 1][gb * HID + gc]) = pack_h2(hv0, hv1);
        *reinterpret_cast<float2*>(out + ((size_t)s * BATCH + gb) * HID + gc) =
            make_float2(hv0, hv1);

        gbar(bg, cta);
        p ^= 1;
    }

    // finals
    float* hf = out + (size_t)SEQ * BATCH * HID;
    float* cf = hf + (size_t)BATCH * HID;
    *reinterpret_cast<float2*>(hf + gb * HID + gc) = make_float2(hv0, hv1);
    *reinterpret_cast<float2*>(cf + gb * HID + gc) = make_float2(c0, c1);
}

// =============================================================================
extern "C" void kernel_launch(void* const* d_in, const int* in_sizes, int n_in,
                              void* d_out, int out_size) {
    const float* x   = (const float*)d_in[0];
    const float* Wih = (const float*)d_in[1];
    const float* Whh = (const float*)d_in[2];
    const float* bih = (const float*)d_in[3];
    const float* bhh = (const float*)d_in[4];
    float* out = (float*)d_out;

    dim3 grid1(16, 1024);
    lstm_xgemm<<<grid1, 256>>>(x, Wih, bih, bhh);

    const int smem2 = 8 * 128 * 18 * (int)sizeof(float);  // 73728
    cudaFuncSetAttribute(lstm_rec3, cudaFuncAttributeMaxDynamicSharedMemorySize, smem2);
    lstm_rec3<<<NG * GSZ, 256, smem2>>>(Whh, out);
}

// round 11
// speedup vs baseline: 2.6528x; 2.6528x over previous
#include <cuda_runtime.h>
#include <cuda_fp16.h>
#include <cstdint>

#define SEQ   2048
#define BATCH 64
#define DIM   512
#define HID   512
#define GATE  2048   // 4*HID
#define NG    4      // independent batch groups (= clusters)
#define GSZ   16     // CTAs per group (= cluster size)
#define BPG   16     // batches per group

// ---------------- device scratch ---------------------------------------------
__device__ float  g_xg[(size_t)SEQ * BATCH * GATE];  // precomputed input gates
__device__ __half g_hh[2][BATCH * HID];              // double-buffered hidden state (fp16)

struct alignas(128) PadU { unsigned v; unsigned pad[31]; };
__device__ PadU g_cnt[NG];   // fallback barrier: per-group arrive counters
__device__ PadU g_gen[NG];   // fallback barrier: per-group generation (monotonic)

// ---------------- helpers ----------------------------------------------------
__device__ __forceinline__ uint32_t pack_h2(float a, float b) {
    __half2 h = __floats2half2_rn(a, b);
    return *reinterpret_cast<uint32_t*>(&h);
}
__device__ __forceinline__ uint32_t ldcg_u32(const void* p) {
    uint32_t v;
    asm volatile("ld.global.cg.b32 %0, [%1];" : "=r"(v) : "l"(p));
    return v;
}
__device__ __forceinline__ void mma_f16(float* c, const uint32_t* a, const uint32_t* b) {
    asm volatile(
        "mma.sync.aligned.m16n8k16.row.col.f32.f16.f16.f32 "
        "{%0,%1,%2,%3}, {%4,%5,%6,%7}, {%8,%9}, {%0,%1,%2,%3};"
        : "+f"(c[0]), "+f"(c[1]), "+f"(c[2]), "+f"(c[3])
        : "r"(a[0]), "r"(a[1]), "r"(a[2]), "r"(a[3]), "r"(b[0]), "r"(b[1]));
}
__device__ __forceinline__ float sigf(float x) { return 1.0f / (1.0f + __expf(-x)); }
__device__ __forceinline__ float tanhfast(float x) { return 2.0f / (1.0f + __expf(-2.0f * x)) - 1.0f; }

// =============================================================================
// Phase 1: Xg = x @ W_ih^T + (b_ih + b_hh)   (unchanged — proven)
// =============================================================================
__global__ __launch_bounds__(256) void lstm_xgemm(
    const float* __restrict__ x, const float* __restrict__ Wih,
    const float* __restrict__ bih, const float* __restrict__ bhh)
{
    __shared__ __half As[128 * 40];
    __shared__ __half Bs[128 * 40];
    __shared__ float  bsum[128];

    const int t = threadIdx.x;
    const int warp = t >> 5, lane = t & 31;
    const int wm = warp & 1;
    const int wn = warp >> 1;
    const int g = lane >> 2, tig = lane & 3;
    const int m0 = blockIdx.y * 128;
    const int n0 = blockIdx.x * 128;

    if (t < 128) bsum[t] = bih[n0 + t] + bhh[n0 + t];

    float acc[4][4][4];
#pragma unroll
    for (int mt = 0; mt < 4; mt++)
#pragma unroll
        for (int nt = 0; nt < 4; nt++)
#pragma unroll
            for (int i = 0; i < 4; i++) acc[mt][nt][i] = 0.f;

    for (int kc = 0; kc < 512; kc += 32) {
        __syncthreads();
#pragma unroll
        for (int i = 0; i < 4; i++) {
            int f = t + i * 256;
            int row = f >> 3, q = (f & 7) * 4;
            float4 v = *reinterpret_cast<const float4*>(x + (size_t)(m0 + row) * 512 + kc + q);
            __half2* d = reinterpret_cast<__half2*>(As + row * 40 + q);
            d[0] = __floats2half2_rn(v.x, v.y);
            d[1] = __floats2half2_rn(v.z, v.w);
        }
#pragma unroll
        for (int i = 0; i < 4; i++) {
            int f = t + i * 256;
            int row = f >> 3, q = (f & 7) * 4;
            float4 v = *reinterpret_cast<const float4*>(Wih + (size_t)(n0 + row) * 512 + kc + q);
            __half2* d = reinterpret_cast<__half2*>(Bs + row * 40 + q);
            d[0] = __floats2half2_rn(v.x, v.y);
            d[1] = __floats2half2_rn(v.z, v.w);
        }
        __syncthreads();

#pragma unroll
        for (int kt = 0; kt < 2; kt++) {
            const int k0 = kt * 16;
            uint32_t a[4][4], b[4][2];
#pragma unroll
            for (int mt = 0; mt < 4; mt++) {
                const int r = wm * 64 + mt * 16;
                a[mt][0] = *reinterpret_cast<const uint32_t*>(As + (r + g)     * 40 + k0 + 2 * tig);
                a[mt][1] = *reinterpret_cast<const uint32_t*>(As + (r + g + 8) * 40 + k0 + 2 * tig);
                a[mt][2] = *reinterpret_cast<const uint32_t*>(As + (r + g)     * 40 + k0 + 2 * tig + 8);
                a[mt][3] = *reinterpret_cast<const uint32_t*>(As + (r + g + 8) * 40 + k0 + 2 * tig + 8);
            }
#pragma unroll
            for (int nt = 0; nt < 4; nt++) {
                const int rn = wn * 32 + nt * 8;
                b[nt][0] = *reinterpret_cast<const uint32_t*>(Bs + (rn + g) * 40 + k0 + 2 * tig);
                b[nt][1] = *reinterpret_cast<const uint32_t*>(Bs + (rn + g) * 40 + k0 + 2 * tig + 8);
            }
#pragma unroll
            for (int mt = 0; mt < 4; mt++)
#pragma unroll
                for (int nt = 0; nt < 4; nt++)
                    mma_f16(acc[mt][nt], a[mt], b[nt]);
        }
    }

#pragma unroll
    for (int mt = 0; mt < 4; mt++) {
        const int r0 = m0 + wm * 64 + mt * 16 + g;
#pragma unroll
        for (int nt = 0; nt < 4; nt++) {
            const int cl = wn * 32 + nt * 8 + 2 * tig;
            const float b0 = bsum[cl], b1 = bsum[cl + 1];
            float2 v0 = make_float2(acc[mt][nt][0] + b0, acc[mt][nt][1] + b1);
            float2 v1 = make_float2(acc[mt][nt][2] + b0, acc[mt][nt][3] + b1);
            *reinterpret_cast<float2*>(g_xg + (size_t)r0 * GATE + n0 + cl)       = v0;
            *reinterpret_cast<float2*>(g_xg + (size_t)(r0 + 8) * GATE + n0 + cl) = v1;
        }
    }
}

// =============================================================================
// Phase 2: batch-partitioned persistent recurrence (R9 body, proven correct).
// 4 independent groups x 16 CTAs. Barrier: HW cluster barrier (group==cluster)
// or single-line sense-reversing L2 flag barrier (fallback).
// =============================================================================
__device__ __forceinline__ void gbar_flag(int bg) {
    __syncthreads();
    if (threadIdx.x == 0) {
        unsigned* cnt = &g_cnt[bg].v;
        unsigned* gen = &g_gen[bg].v;
        unsigned gv;
        asm volatile("ld.acquire.gpu.global.u32 %0, [%1];" : "=r"(gv) : "l"(gen) : "memory");
        unsigned old;
        asm volatile("atom.acq_rel.gpu.global.add.u32 %0, [%1], %2;"
                     : "=r"(old) : "l"(cnt), "r"(1u) : "memory");
        if (old == GSZ - 1u) {
            asm volatile("st.relaxed.gpu.global.u32 [%0], %1;" :: "l"(cnt), "r"(0u) : "memory");
            asm volatile("st.release.gpu.global.u32 [%0], %1;" :: "l"(gen), "r"(gv + 1u) : "memory");
        } else {
            unsigned cur;
            while (true) {
                asm volatile("ld.acquire.gpu.global.u32 %0, [%1];" : "=r"(cur) : "l"(gen) : "memory");
                if (cur != gv) break;
                __nanosleep(40);
            }
        }
    }
    __syncthreads();
}

template<bool CLUSTER>
__device__ __forceinline__ void gbar(int bg) {
    if (CLUSTER) {
        __syncthreads();
        asm volatile("barrier.cluster.arrive.aligned;" ::: "memory");
        asm volatile("barrier.cluster.wait.aligned;" ::: "memory");
    } else {
        gbar_flag(bg);
    }
}

template<bool CLUSTER>
__global__ __launch_bounds__(256, 1) void lstm_rec3(const float* __restrict__ Whh,
                                                    float* __restrict__ out)
{
    extern __shared__ float part[];   // [8 warps][128 rows][18] = 73728 B
    const int t = threadIdx.x, warp = t >> 5, lane = t & 31;
    const int g = lane >> 2, tig = lane & 3;
    const int bg  = blockIdx.x >> 4;       // batch group 0..3
    const int C0  = (blockIdx.x & 15) * 32; // h-col base
    const int NB0 = bg * BPG;              // batch base
    const int ks  = warp * 64;             // this warp's k-slice

    // ---- resident W_hh fragments: 128 packed rows (m = q*32 + j), fp16 ----
    uint32_t wfr[8][4][4];                 // [mtile][ktile][reg] = 128 regs
#pragma unroll
    for (int mt = 0; mt < 8; mt++) {
        const int row_lo = mt * 16 + g;
        const int row_hi = row_lo + 8;
        const float* wlo = Whh + (size_t)((row_lo >> 5) * 512 + C0 + (row_lo & 31)) * 512;
        const float* whi = Whh + (size_t)((row_hi >> 5) * 512 + C0 + (row_hi & 31)) * 512;
#pragma unroll
        for (int kt = 0; kt < 4; kt++) {
            const int k = ks + kt * 16 + 2 * tig;
            wfr[mt][kt][0] = pack_h2(wlo[k],     wlo[k + 1]);
            wfr[mt][kt][1] = pack_h2(whi[k],     whi[k + 1]);
            wfr[mt][kt][2] = pack_h2(wlo[k + 8], wlo[k + 9]);
            wfr[mt][kt][3] = pack_h2(whi[k + 8], whi[k + 9]);
        }
    }

    // output mapping: thread owns (batch cb, col pair cp)
    const int cb = t >> 4;                 // 0..15 local batch
    const int cp = t & 15;                 // 0..15 col pair
    const int gb = NB0 + cb;               // global batch
    const int gc = C0 + 2 * cp;            // global h-col

    // init h0 = 0 for this CTA's (batch, col) slice
    *reinterpret_cast<uint32_t*>(&g_hh[0][gb * HID + gc]) = 0u;
    float c0 = 0.f, c1 = 0.f, hv0 = 0.f, hv1 = 0.f;

    gbar<CLUSTER>(bg);

    int p = 0;
    for (int s = 0; s < SEQ; s++) {
        // ---- B fragments: h[16 batches, k-slice] from L2 ----
        uint32_t bb[2][4][2];
        const __half* hsrc = g_hh[p];
#pragma unroll
        for (int nt = 0; nt < 2; nt++)
#pragma unroll
            for (int kt = 0; kt < 4; kt++) {
                const __half* hp = hsrc + (size_t)(NB0 + nt * 8 + g) * HID + ks + kt * 16 + 2 * tig;
                bb[nt][kt][0] = ldcg_u32(hp);
                bb[nt][kt][1] = ldcg_u32(hp + 8);
            }

        // ---- Xg loads (independent; fill load latency) ----
        float xg[4][2];
        {
            const float* xb = g_xg + ((size_t)s * BATCH + gb) * GATE + gc;
#pragma unroll
            for (int q = 0; q < 4; q++) {
                float2 u = *reinterpret_cast<const float2*>(xb + q * 512);
                xg[q][0] = u.x; xg[q][1] = u.y;
            }
        }

        // ---- 64 mma: gates[128, 16] partial over this warp's K=64 ----
        float acc[8][2][4];
#pragma unroll
        for (int mt = 0; mt < 8; mt++)
#pragma unroll
            for (int nt = 0; nt < 2; nt++)
#pragma unroll
                for (int i = 0; i < 4; i++) acc[mt][nt][i] = 0.f;
#pragma unroll
        for (int kt = 0; kt < 4; kt++)
#pragma unroll
            for (int mt = 0; mt < 8; mt++)
#pragma unroll
                for (int nt = 0; nt < 2; nt++)
                    mma_f16(acc[mt][nt], wfr[mt][kt], bb[nt][kt]);

        // ---- store k-partials: [warp][row 128][batch 16 pad 18] ----
        float* pw = part + warp * (128 * 18);
#pragma unroll
        for (int mt = 0; mt < 8; mt++)
#pragma unroll
            for (int nt = 0; nt < 2; nt++) {
                const int row = mt * 16 + g, col = nt * 8 + 2 * tig;
                *reinterpret_cast<float2*>(pw + row * 18 + col) =
                    make_float2(acc[mt][nt][0], acc[mt][nt][1]);
                *reinterpret_cast<float2*>(pw + (row + 8) * 18 + col) =
                    make_float2(acc[mt][nt][2], acc[mt][nt][3]);
            }
        __syncthreads();

        // ---- reduce 8 partials + activations + state update ----
        float sg[4][2];
#pragma unroll
        for (int q = 0; q < 4; q++)
#pragma unroll
            for (int jj = 0; jj < 2; jj++) {
                const int row = q * 32 + 2 * cp + jj;
                const int base = row * 18 + cb;
                float v = part[base];
#pragma unroll
                for (int w = 1; w < 8; w++) v += part[w * (128 * 18) + base];
                sg[q][jj] = v;
            }

        const float i0 = sigf(xg[0][0] + sg[0][0]);
        const float i1 = sigf(xg[0][1] + sg[0][1]);
        const float f0 = sigf(xg[1][0] + sg[1][0]);
        const float f1 = sigf(xg[1][1] + sg[1][1]);
        const float g0 = tanhfast(xg[2][0] + sg[2][0]);
        const float g1 = tanhfast(xg[2][1] + sg[2][1]);
        const float o0 = sigf(xg[3][0] + sg[3][0]);
        const float o1 = sigf(xg[3][1] + sg[3][1]);

        c0 = f0 * c0 + i0 * g0;
        c1 = f1 * c1 + i1 * g1;
        hv0 = o0 * tanhfast(c0);
        hv1 = o1 * tanhfast(c1);

        // publish h (fp16, plain store — ordered by barrier release/acquire) + output
        *reinterpret_cast<uint32_t*>(&g_hh[p ^ 1][gb * HID + gc]) = pack_h2(hv0, hv1);
        *reinterpret_cast<float2*>(out + ((size_t)s * BATCH + gb) * HID + gc) =
            make_float2(hv0, hv1);

        gbar<CLUSTER>(bg);
        p ^= 1;
    }

    // finals
    float* hf = out + (size_t)SEQ * BATCH * HID;
    float* cf = hf + (size_t)BATCH * HID;
    *reinterpret_cast<float2*>(hf + gb * HID + gc) = make_float2(hv0, hv1);
    *reinterpret_cast<float2*>(cf + gb * HID + gc) = make_float2(c0, c1);
}

// =============================================================================
extern "C" void kernel_launch(void* const* d_in, const int* in_sizes, int n_in,
                              void* d_out, int out_size) {
    const float* x   = (const float*)d_in[0];
    const float* Wih = (const float*)d_in[1];
    const float* Whh = (const float*)d_in[2];
    const float* bih = (const float*)d_in[3];
    const float* bhh = (const float*)d_in[4];
    float* out = (float*)d_out;

    dim3 grid1(16, 1024);
    lstm_xgemm<<<grid1, 256>>>(x, Wih, bih, bhh);

    const int smem2 = 8 * 128 * 18 * (int)sizeof(float);  // 73728

    // Deterministic cluster capability check (same result every call).
    int maxc = 0;
    cudaError_t e1 = cudaFuncSetAttribute(lstm_rec3<true>,
                                          cudaFuncAttributeMaxDynamicSharedMemorySize, smem2);
    cudaError_t e2 = cudaFuncSetAttribute(lstm_rec3<true>,
                                          cudaFuncAttributeNonPortableClusterSizeAllowed, 1);
    if (e1 == cudaSuccess && e2 == cudaSuccess) {
        cudaLaunchConfig_t qcfg = {};
        qcfg.gridDim = dim3(NG * GSZ, 1, 1);
        qcfg.blockDim = dim3(256, 1, 1);
        qcfg.dynamicSmemBytes = smem2;
        if (cudaOccupancyMaxPotentialClusterSize(&maxc, lstm_rec3<true>, &qcfg) != cudaSuccess)
            maxc = 0;
    }

    if (maxc >= GSZ) {
        cudaLaunchConfig_t cfg = {};
        cfg.gridDim = dim3(NG * GSZ, 1, 1);
        cfg.blockDim = dim3(256, 1, 1);
        cfg.dynamicSmemBytes = smem2;
        cudaLaunchAttribute attrs[1];
        attrs[0].id = cudaLaunchAttributeClusterDimension;
        attrs[0].val.clusterDim.x = GSZ;
        attrs[0].val.clusterDim.y = 1;
        attrs[0].val.clusterDim.z = 1;
        cfg.attrs = attrs;
        cfg.numAttrs = 1;
        cudaLaunchKernelEx(&cfg, lstm_rec3<true>, Whh, out);
    } else {
        cudaFuncSetAttribute(lstm_rec3<false>,
                             cudaFuncAttributeMaxDynamicSharedMemorySize, smem2);
        lstm_rec3<false><<<NG * GSZ, 256, smem2>>>(Whh, out);
    }
}